// round 12
// baseline (speedup 1.0000x reference)
#include <cuda_runtime.h>
#include <cstdint>

// Problem constants
#define BB   512
#define TT   65536
#define CL   256                  // chunk length (samples per thread)
#define NC   (TT / CL)            // 256 chunks per row
#define WUP  10                   // warm-up stages of 16 samples (160 total)
#define OWN  16                   // own-chunk stages of 16 samples
#define NST  (WUP + OWN)          // 26
#define NTH  128                  // 4 warps; each warp owns 32 chunks
#define NRP  (BB / 2)             // 256 row pairs
#define GRID (NRP * 2)            // 512 blocks

// fwd smem: 4 warps x 2 parities x 2 rows x (32 chunks * 5 float4) = 2560 float4
#define FWD_WARP_F4  (2 * 2 * 32 * 5)     // 640 float4 per warp
#define SMEM_FWD     (4 * FWD_WARP_F4 * 16)   // 40960 B
// bwd smem: output staging, 2 rows x 128 threads x 9 float4
#define BWD_BUF_F4   (NTH * 9)
#define SMEM_BWD     (2 * BWD_BUF_F4 * 16)    // 36864 B

typedef unsigned long long u64f;

// Intermediate: y1 transposed-packed: yt[iw * NC + c]; packs the row pair.
__device__ __align__(16) u64f g_y1t[(size_t)NRP * TT];   // 128 MB

// ---------------------------------------------------------------------------
#define FFMA2(d, a, b, c) asm("fma.rn.f32x2 %0, %1, %2, %3;" : "=l"(d) : "l"(a), "l"(b), "l"(c))

__device__ __forceinline__ u64f pk2(float lo, float hi) {
    u64f r; asm("mov.b64 %0, {%1, %2};" : "=l"(r) : "f"(lo), "f"(hi)); return r;
}
__device__ __forceinline__ float2 upk(u64f v) {
    float2 r; asm("mov.b64 {%0, %1}, %2;" : "=f"(r.x), "=f"(r.y) : "l"(v)); return r;
}

__device__ __forceinline__ u64f pstep(u64f x, u64f* z, const u64f* cb, const u64f* cna) {
    u64f y, t;
    FFMA2(y, cb[0], x, z[0]);
    #pragma unroll
    for (int i = 0; i < 7; i++) {
        FFMA2(t, cb[i + 1], x, z[i + 1]);
        FFMA2(z[i], cna[i], y, t);
    }
    u64f zz = 0ULL;
    FFMA2(t, cb[8], x, zz);
    FFMA2(z[7], cna[7], y, t);
    return y;
}

__device__ __forceinline__ void load_coef_inline(const float* __restrict__ bp,
                                                 const float* __restrict__ ap,
                                                 u64f* cb, u64f* cna) {
    float inv = 1.0f / __ldg(&ap[0]);
    #pragma unroll
    for (int i = 0; i < 9; i++) {
        float bn = __ldg(&bp[i]) * inv;
        cb[i] = pk2(bn, bn);
    }
    #pragma unroll
    for (int i = 1; i < 9; i++) {
        float an = -(__ldg(&ap[i]) * inv);
        cna[i - 1] = pk2(an, an);
    }
}

// Issue one 16-sample stage's cp.async copies (8 x 16B per lane, both rows).
// Stage k covers samples (chunk*16 + k - WUP)*16 ... negative => zero-fill.
__device__ __forceinline__ void fwd_issue(const float* __restrict__ p0,
                                          const float* __restrict__ p1,
                                          uint32_t sb, int wcb, int ln,
                                          int k, int par) {
    #pragma unroll
    for (int l = 0; l < 4; l++) {
        int q = l * 32 + ln;
        int tt = q >> 2, j = q & 3;
        int s16 = (wcb + tt) * 16 + (k - WUP);   // 16-sample-block index in row
        bool ok = (s16 >= 0);
        int goff = ok ? (s16 * 16 + 4 * j) : 0;  // float offset (16B aligned)
        int sz = ok ? 16 : 0;
        uint32_t d0 = sb + (uint32_t)((((par << 1) + 0) * 160 + tt * 5 + j) * 16);
        uint32_t d1 = sb + (uint32_t)((((par << 1) + 1) * 160 + tt * 5 + j) * 16);
        asm volatile("cp.async.ca.shared.global [%0], [%1], 16, %2;"
                     :: "r"(d0), "l"(p0 + goff), "r"(sz));
        asm volatile("cp.async.ca.shared.global [%0], [%1], 16, %2;"
                     :: "r"(d1), "l"(p1 + goff), "r"(sz));
    }
}

// ---------------------------------------------------------------------------
// fwd: warp-autonomous, cp.async double-buffered 16-sample stages. Warm-up =
// 160 samples preceding the chunk, then 256 own samples; y written to y1T
// inline (coalesced STG.64 across lanes). Loads for stage k+1 are in flight
// during stage k's compute -> no exposed gmem latency.
// ---------------------------------------------------------------------------
__global__ void __launch_bounds__(NTH) fwd_k(const float* __restrict__ x,
                                             const float* __restrict__ bp,
                                             const float* __restrict__ ap) {
    extern __shared__ char smc[];
    int rp = blockIdx.x >> 1, h = blockIdx.x & 1, t = threadIdx.x;
    int w = t >> 5, ln = t & 31;
    int wcb = (h * 4 + w) * 32;          // warp's first chunk
    int c = wcb + ln;                    // this lane's chunk
    const float* p0 = x + (size_t)(rp * 2) * TT;
    const float* p1 = p0 + TT;
    u64f* yt = g_y1t + (size_t)rp * TT;

    float4* wb = (float4*)smc + w * FWD_WARP_F4;
    uint32_t sb = (uint32_t)__cvta_generic_to_shared(wb);

    u64f cb[9], cna[8];
    load_coef_inline(bp, ap, cb, cna);

    u64f z[8];
    #pragma unroll
    for (int i2 = 0; i2 < 8; i2++) z[i2] = 0ULL;

    // prologue: stage 0 into parity 0
    fwd_issue(p0, p1, sb, wcb, ln, 0, 0);
    asm volatile("cp.async.commit_group;" ::: "memory");

    #pragma unroll 1
    for (int k = 0; k < NST; k++) {
        int par = k & 1;
        if (k + 1 < NST) {
            __syncwarp();   // all lanes done consuming stage k-1 (same buffer)
            fwd_issue(p0, p1, sb, wcb, ln, k + 1, par ^ 1);
            asm volatile("cp.async.commit_group;" ::: "memory");
            asm volatile("cp.async.wait_group 1;" ::: "memory");
        } else {
            asm volatile("cp.async.wait_group 0;" ::: "memory");
        }
        __syncwarp();       // stage k's data visible warp-wide

        float4* c0 = wb + ((par << 1) + 0) * 160 + ln * 5;
        float4* c1 = wb + ((par << 1) + 1) * 160 + ln * 5;
        if (k < WUP) {
            #pragma unroll
            for (int j2 = 0; j2 < 4; j2++) {
                float4 a4 = c0[j2];
                float4 c4 = c1[j2];
                pstep(pk2(a4.x, c4.x), z, cb, cna);
                pstep(pk2(a4.y, c4.y), z, cb, cna);
                pstep(pk2(a4.z, c4.z), z, cb, cna);
                pstep(pk2(a4.w, c4.w), z, cb, cna);
            }
        } else {
            #pragma unroll
            for (int j2 = 0; j2 < 4; j2++) {
                float4 a4 = c0[j2];
                float4 c4 = c1[j2];
                u64f yp0 = pstep(pk2(a4.x, c4.x), z, cb, cna);
                u64f yp1 = pstep(pk2(a4.y, c4.y), z, cb, cna);
                u64f yp2 = pstep(pk2(a4.z, c4.z), z, cb, cna);
                u64f yp3 = pstep(pk2(a4.w, c4.w), z, cb, cna);
                int iw = (k - WUP) * 16 + 4 * j2;
                yt[(size_t)(iw + 0) * NC + c] = yp0;
                yt[(size_t)(iw + 1) * NC + c] = yp1;
                yt[(size_t)(iw + 2) * NC + c] = yp2;
                yt[(size_t)(iw + 3) * NC + c] = yp3;
            }
        }
    }
}

// ---------------------------------------------------------------------------
// bwd: warp-autonomous time-reversed filter over y1T. Direct coalesced LDG.64
// with DEPTH-2 rolling register prefetch (8 samples ahead). Output staged to
// physical layout via warp-private smem (+__syncwarp only).
// ---------------------------------------------------------------------------
__global__ void __launch_bounds__(NTH) bwd_k(float* __restrict__ out,
                                             const float* __restrict__ bp,
                                             const float* __restrict__ ap) {
    extern __shared__ char smc[];
    float4* b0 = (float4*)smc;
    float4* b1 = b0 + BWD_BUF_F4;

    int rp = blockIdx.x >> 1, h = blockIdx.x & 1, t = threadIdx.x;
    int w = t >> 5, ln = t & 31;
    int wcb = (h * 4 + w) * 32;
    int c = wcb + ln;
    const u64f* yt = g_y1t + (size_t)rp * TT;
    float* o0 = out + (size_t)(rp * 2) * TT;
    float* o1 = o0 + TT;

    float4* w0 = b0 + w * (32 * 9);
    float4* w1 = b1 + w * (32 * 9);

    u64f cb[9], cna[8];
    load_coef_inline(bp, ap, cb, cna);

    u64f z[8];
    #pragma unroll
    for (int i2 = 0; i2 < 8; i2++) z[i2] = 0ULL;

    // ---- warm-up: chunk c+1, iw = 159 down to 0, depth-2 prefetch ----
    {
        bool valid = (c + 1 < NC);
        const u64f* base = yt + (valid ? (c + 1) : c);
        u64f A0, A1, A2, A3, B0, B1, B2, B3;
        A3 = valid ? base[(size_t)159 * NC] : 0ULL;
        A2 = valid ? base[(size_t)158 * NC] : 0ULL;
        A1 = valid ? base[(size_t)157 * NC] : 0ULL;
        A0 = valid ? base[(size_t)156 * NC] : 0ULL;
        B3 = valid ? base[(size_t)155 * NC] : 0ULL;
        B2 = valid ? base[(size_t)154 * NC] : 0ULL;
        B1 = valid ? base[(size_t)153 * NC] : 0ULL;
        B0 = valid ? base[(size_t)152 * NC] : 0ULL;
        #pragma unroll 2
        for (int p = 0; p < 40; p++) {
            u64f x3 = A3, x2 = A2, x1 = A1, x0 = A0;
            A3 = B3; A2 = B2; A1 = B1; A0 = B0;
            int nt = 159 - 4 * (p + 2);
            if (p + 2 < 40) {
                B3 = valid ? base[(size_t)(nt - 0) * NC] : 0ULL;
                B2 = valid ? base[(size_t)(nt - 1) * NC] : 0ULL;
                B1 = valid ? base[(size_t)(nt - 2) * NC] : 0ULL;
                B0 = valid ? base[(size_t)(nt - 3) * NC] : 0ULL;
            }
            pstep(x3, z, cb, cna);
            pstep(x2, z, cb, cna);
            pstep(x1, z, cb, cna);
            pstep(x0, z, cb, cna);
        }
    }

    // ---- own chunk: iw = 255 down to 0, depth-2 prefetch, staged output ----
    {
        const u64f* base = yt + c;
        u64f A0, A1, A2, A3, B0, B1, B2, B3;
        A3 = base[(size_t)255 * NC];
        A2 = base[(size_t)254 * NC];
        A1 = base[(size_t)253 * NC];
        A0 = base[(size_t)252 * NC];
        B3 = base[(size_t)251 * NC];
        B2 = base[(size_t)250 * NC];
        B1 = base[(size_t)249 * NC];
        B0 = base[(size_t)248 * NC];
        #pragma unroll 1
        for (int g = 0; g < 8; g++) {
            int iwb = 224 - 32 * g;          // base of this 32-sample group
            #pragma unroll
            for (int g4 = 0; g4 < 8; g4++) {
                int p = g * 8 + g4;
                u64f x3 = A3, x2 = A2, x1 = A1, x0 = A0;
                A3 = B3; A2 = B2; A1 = B1; A0 = B0;
                int nt = 255 - 4 * (p + 2);
                if (p + 2 < 64) {
                    B3 = base[(size_t)(nt - 0) * NC];
                    B2 = base[(size_t)(nt - 1) * NC];
                    B1 = base[(size_t)(nt - 2) * NC];
                    B0 = base[(size_t)(nt - 3) * NC];
                }
                float2 y3 = upk(pstep(x3, z, cb, cna));   // iw3
                float2 y2 = upk(pstep(x2, z, cb, cna));   // iw3-1
                float2 y1v = upk(pstep(x1, z, cb, cna));  // iw3-2
                float2 y0 = upk(pstep(x0, z, cb, cna));   // iw3-3
                int jl = 7 - g4;
                w0[ln * 9 + jl] = make_float4(y0.x, y1v.x, y2.x, y3.x);
                w1[ln * 9 + jl] = make_float4(y0.y, y1v.y, y2.y, y3.y);
            }
            __syncwarp();
            #pragma unroll
            for (int l = 0; l < 8; l++) {
                int q = l * 32 + ln;
                int tt = q >> 3, j = q & 7;
                int cc = wcb + tt;
                int base2 = cc * CL + iwb + 4 * j;
                *reinterpret_cast<float4*>(o0 + base2) = w0[tt * 9 + j];
                *reinterpret_cast<float4*>(o1 + base2) = w1[tt * 9 + j];
            }
            __syncwarp();
        }
    }
}

extern "C" void kernel_launch(void* const* d_in, const int* in_sizes, int n_in,
                              void* d_out, int out_size) {
    const float* x = (const float*)d_in[0];
    const float* b = (const float*)d_in[1];
    const float* a = (const float*)d_in[2];
    float* out = (float*)d_out;

    static bool attr_done = false;
    if (!attr_done) {
        cudaFuncSetAttribute(fwd_k, cudaFuncAttributeMaxDynamicSharedMemorySize, SMEM_FWD);
        cudaFuncSetAttribute(bwd_k, cudaFuncAttributeMaxDynamicSharedMemorySize, SMEM_BWD);
        attr_done = true;
    }

    fwd_k<<<GRID, NTH, SMEM_FWD>>>(x, b, a);
    bwd_k<<<GRID, NTH, SMEM_BWD>>>(out, b, a);
}